// round 8
// baseline (speedup 1.0000x reference)
#include <cuda_runtime.h>
#include <cuda_bf16.h>
#include <cstdint>

#define T_STEPS 512
#define N_BATCH 64
#define C_IN    512
#define H_DIM   1024
#define P_DIM   512
#define G4H     4096
#define M_TOTAL (T_STEPS * N_BATCH)   /* 32768 */
#define NBLK    128
#define NTHR    512
#define KSPLIT  1536                  /* pre-GEMM bf16-split K */

typedef unsigned long long u64t;

// ---------------- scratch (device globals: no runtime allocation allowed) -------------
__device__ float g_pre[(size_t)G4H * M_TOTAL];        // pre^T [g][m], 512 MB
__device__ __nv_bfloat16 g_rb[2][N_BATCH * 1024];     // r state (ping-pong): [n][hi|lo]
__device__ __nv_bfloat16 g_hb[2][N_BATCH * 2048];     // h state (ping-pong): [n][hi|lo]
__device__ unsigned g_count;                          // legacy barrier counter
__device__ unsigned g_sense;                          // legacy barrier sense
__device__ unsigned g_flags[NBLK * 64];               // per-CTA progress flag (256B/line)
__device__ __nv_bfloat16 g_xs[(size_t)M_TOTAL * KSPLIT];  // x split  [m][1536]
__device__ __nv_bfloat16 g_ws[(size_t)G4H * KSPLIT];      // wx split [g][1536]

// ---------------- small helpers --------------------------------------------------------
__device__ __forceinline__ void cpa16s(uint32_t smem_dst, const void* gsrc) {
    asm volatile("cp.async.cg.shared.global [%0], [%1], 16;" :: "r"(smem_dst), "l"(gsrc));
}
#define CP_COMMIT() asm volatile("cp.async.commit_group;" ::: "memory")
#define CP_WAIT0()  asm volatile("cp.async.wait_group 0;" ::: "memory")
#define CP_WAIT1()  asm volatile("cp.async.wait_group 1;" ::: "memory")

__device__ __forceinline__ float sigmoidf_(float x) {
    return 1.0f / (1.0f + __expf(-x));
}
__device__ __forceinline__ float tanhf_(float x) {
    float e = __expf(-2.0f * fabsf(x));
    float t = (1.0f - e) / (1.0f + e);
    return copysignf(t, x);
}
__device__ __forceinline__ uint32_t smem_u32(const void* p) {
    return (uint32_t)__cvta_generic_to_shared(p);
}
__device__ __forceinline__ void stcg_u32(void* p, uint32_t v) {
    asm volatile("st.global.cg.u32 [%0], %1;" :: "l"(p), "r"(v) : "memory");
}
__device__ __forceinline__ void stcg_u16(void* p, unsigned short v) {
    asm volatile("st.global.cg.u16 [%0], %1;" :: "l"(p), "h"(v) : "memory");
}
__device__ __forceinline__ unsigned short bf_bits(__nv_bfloat16 h) {
    unsigned short u; __builtin_memcpy(&u, &h, 2); return u;
}

// ---------------- HMMA helpers (sm_80+ baseline PTX: valid at compute_103) ------------
__device__ __forceinline__ void ldm_x4(uint32_t &r0, uint32_t &r1, uint32_t &r2,
                                       uint32_t &r3, uint32_t a) {
    asm volatile("ldmatrix.sync.aligned.m8n8.x4.shared.b16 {%0,%1,%2,%3}, [%4];"
                 : "=r"(r0), "=r"(r1), "=r"(r2), "=r"(r3) : "r"(a));
}
__device__ __forceinline__ void ldm_x2(uint32_t &r0, uint32_t &r1, uint32_t a) {
    asm volatile("ldmatrix.sync.aligned.m8n8.x2.shared.b16 {%0,%1}, [%2];"
                 : "=r"(r0), "=r"(r1) : "r"(a));
}
__device__ __forceinline__ void mma_bf16(float* d, const uint32_t* a, const uint32_t* b) {
    asm volatile("mma.sync.aligned.m16n8k16.row.col.f32.bf16.bf16.f32 "
                 "{%0,%1,%2,%3}, {%4,%5,%6,%7}, {%8,%9}, {%0,%1,%2,%3};"
                 : "+f"(d[0]), "+f"(d[1]), "+f"(d[2]), "+f"(d[3])
                 : "r"(a[0]), "r"(a[1]), "r"(a[2]), "r"(a[3]),
                   "r"(b[0]), "r"(b[1]));
}

// ---------------- legacy atomic grid barrier (2x per lstm_rec launch) -----------------
__device__ __forceinline__ void grid_barrier(unsigned &sense_local) {
    __syncthreads();
    if (threadIdx.x == 0) {
        unsigned s = sense_local ^ 1u;
        unsigned prev;
        asm volatile("atom.acq_rel.gpu.global.add.u32 %0, [%1], %2;"
                     : "=r"(prev) : "l"(&g_count), "r"(1u) : "memory");
        if (prev == gridDim.x - 1) {
            g_count = 0;
            asm volatile("st.release.gpu.global.u32 [%0], %1;"
                         :: "l"(&g_sense), "r"(s) : "memory");
        } else {
            unsigned v;
            do {
                asm volatile("ld.acquire.gpu.global.u32 %0, [%1];"
                             : "=r"(v) : "l"(&g_sense) : "memory");
            } while (v != s);
        }
    }
    __syncthreads();
    sense_local ^= 1u;
}

// ---------------- partial-order sync --------------------------------------------------
// Wait for 32 producer CTAs (group) to reach flag >= target. Warp 0 polls (one flag
// per lane, distinct 256B lines), then CTA-wide sync publishes the result.
__device__ __forceinline__ void waitg(int group, unsigned target) {
    if (threadIdx.x < 32) {
        const unsigned* p = &g_flags[(group * 32 + threadIdx.x) * 64];
        unsigned v;
        do {
            asm volatile("ld.acquire.gpu.global.u32 %0, [%1];"
                         : "=r"(v) : "l"(p) : "memory");
        } while ((int)(v - target) < 0);
    }
    __syncthreads();
}
// Publish progress. Preceded by __syncthreads() at call sites, so the release is
// cumulative over all CTA threads' prior st.cg stores.
__device__ __forceinline__ void setflag(unsigned v) {
    asm volatile("st.release.gpu.global.u32 [%0], %1;"
                 :: "l"(&g_flags[blockIdx.x * 64]), "r"(v) : "memory");
}

// ---------------- Kernel 0: fp32 -> bf16 split, K-concatenated (pre-GEMM operands) ----
__global__ void split3(const float* __restrict__ src, __nv_bfloat16* __restrict__ dst,
                       int total, int mode) {
    for (int i = blockIdx.x * blockDim.x + threadIdx.x; i < total;
         i += gridDim.x * blockDim.x) {
        int row = i >> 9, k = i & 511;
        float v = src[i];
        __nv_bfloat16 h = __float2bfloat16(v);
        __nv_bfloat16 l = __float2bfloat16(v - __bfloat162float(h));
        __nv_bfloat16* d = dst + (size_t)row * KSPLIT + k;
        d[0] = h;
        d[512]  = mode ? h : l;
        d[1024] = mode ? l : h;
    }
}

// ---------------- Kernel 1: HMMA bf16-split pre-GEMM (unchanged, passing) -------------
#define PBM 256
#define PBN 128
#define PTHR 512
#define A_STG 20480
#define B_STG 10240
#define STG   (A_STG + B_STG)
#define PRE_SMEM (2 * STG)

__global__ __launch_bounds__(PTHR, 1)
void hmma_pre(const float* __restrict__ Bb) {
    extern __shared__ char smc[];
    const uint32_t sb = smem_u32(smc);
    const int tid = threadIdx.x, lane = tid & 31, warp = tid >> 5;
    const int wg = warp >> 2;
    const int wm = warp & 3;
    const int g0 = blockIdx.x * PBM;
    const int m0 = blockIdx.y * PBN;

    float acc[4][4][4];
#pragma unroll
    for (int a = 0; a < 4; a++)
#pragma unroll
        for (int b = 0; b < 4; b++)
#pragma unroll
            for (int c = 0; c < 4; c++) acc[a][b][c] = 0.0f;

    const int a_r = lane & 15;
    const int a_k = (lane & 16) ? 8 : 0;
    const int b_r = (lane & 7) + ((lane & 16) ? 8 : 0);
    const int b_k = (lane & 8) ? 8 : 0;

#pragma unroll 1
    for (int c = 0; c < KSPLIT / 32 + 1; c++) {
        if (c < KSPLIT / 32) {
            const int k0 = c * 32;
            const uint32_t ba = sb + (c & 1) * STG;
#pragma unroll
            for (int s = 0; s < 3; s++) {
                int f = tid + s * PTHR;
                if (f < 1024) {
                    int row = f >> 2, seg = f & 3;
                    cpa16s(ba + row * 80 + seg * 16,
                           g_ws + (size_t)(g0 + row) * KSPLIT + k0 + seg * 8);
                } else {
                    int f2 = f - 1024;
                    int row = f2 >> 2, seg = f2 & 3;
                    cpa16s(ba + A_STG + row * 80 + seg * 16,
                           g_xs + (size_t)(m0 + row) * KSPLIT + k0 + seg * 8);
                }
            }
            CP_COMMIT();
        }
        if (c == 0) continue;
        const int cc = c - 1;
        if (c < KSPLIT / 32) CP_WAIT1(); else CP_WAIT0();
        __syncthreads();

        const uint32_t abase = sb + (cc & 1) * STG + (wg * 64 + a_r) * 80 + a_k * 2;
        const uint32_t bbase = sb + (cc & 1) * STG + A_STG + (wm * 32 + b_r) * 80 + b_k * 2;
#pragma unroll
        for (int kh = 0; kh < 2; kh++) {
            uint32_t af[4][4], bf[2][4];
#pragma unroll
            for (int gi = 0; gi < 4; gi++)
                ldm_x4(af[gi][0], af[gi][1], af[gi][2], af[gi][3],
                       abase + gi * 16 * 80 + kh * 32);
#pragma unroll
            for (int bj = 0; bj < 2; bj++)
                ldm_x4(bf[bj][0], bf[bj][1], bf[bj][2], bf[bj][3],
                       bbase + bj * 16 * 80 + kh * 32);
#pragma unroll
            for (int gi = 0; gi < 4; gi++)
#pragma unroll
                for (int mj = 0; mj < 4; mj++)
                    mma_bf16(acc[gi][mj], af[gi], &bf[mj >> 1][(mj & 1) * 2]);
        }
        __syncthreads();
    }

#pragma unroll
    for (int gi = 0; gi < 4; gi++) {
        const int gr = g0 + wg * 64 + gi * 16 + (lane >> 2);
        const float blo = __ldg(Bb + gr);
        const float bhi = __ldg(Bb + gr + 8);
#pragma unroll
        for (int mj = 0; mj < 4; mj++) {
            const int mc = m0 + wm * 32 + mj * 8 + (lane & 3) * 2;
            float2 v0 = { acc[gi][mj][0] + blo, acc[gi][mj][1] + blo };
            float2 v1 = { acc[gi][mj][2] + bhi, acc[gi][mj][3] + bhi };
            *(float2*)(g_pre + (size_t)gr * M_TOTAL + mc) = v0;
            *(float2*)(g_pre + (size_t)(gr + 8) * M_TOTAL + mc) = v1;
        }
    }
}

// ---------------- Kernel 2: persistent LSTM recurrence (HMMA + partial-order sync) ----
// smem layout identical to R6.
#define R_REG   0
#define R_W1HI  133120
#define R_W1LO  166400
#define R_WOHI  199680
#define R_WOLO  207936
#define REC_SMEM 216192
#define HBUF1   66560

__global__ __launch_bounds__(NTHR, 1)
void lstm_rec(const float* __restrict__ WR, const float* __restrict__ WO,
              const float* __restrict__ WC, const void* __restrict__ Lraw,
              float* __restrict__ out) {
    extern __shared__ char sm[];
    const uint32_t sb = smem_u32(sm);
    float* part  = (float*)(sm + R_REG);
    float* part3 = (float*)(sm + R_REG);

    const int tid = threadIdx.x;
    const int blk = blockIdx.x;
    const int lane = tid & 31, warp = tid >> 5;
    const int grot = blk >> 5;                // this CTA's producer group (chunk rotation)

    // ---- build static weights in smem (bf16 hi/lo) ----
    {
        __nv_bfloat16* w1h = (__nv_bfloat16*)(sm + R_W1HI);
        __nv_bfloat16* w1l = (__nv_bfloat16*)(sm + R_W1LO);
        for (int idx = tid; idx < 32 * 512; idx += NTHR) {
            int gcol = idx >> 9, k = idx & 511;
            int gate = gcol >> 3, hl = gcol & 7;
            float v = WR[(size_t)(gate * H_DIM + blk * 8 + hl) * P_DIM + k];
            __nv_bfloat16 h = __float2bfloat16(v);
            w1h[gcol * 520 + k] = h;
            w1l[gcol * 520 + k] = __float2bfloat16(v - __bfloat162float(h));
        }
        __nv_bfloat16* woh = (__nv_bfloat16*)(sm + R_WOHI);
        __nv_bfloat16* wol = (__nv_bfloat16*)(sm + R_WOLO);
        for (int idx = tid; idx < 4 * 1024; idx += NTHR) {
            int p = idx >> 10, k = idx & 1023;
            float v = WO[(size_t)(blk * 4 + p) * H_DIM + k];
            __nv_bfloat16 h = __float2bfloat16(v);
            woh[p * 1032 + k] = h;
            wol[p * 1032 + k] = __float2bfloat16(v - __bfloat162float(h));
        }
    }

    // ---- roles (identical to R6) ----
    const int mh  = warp & 1;
    const int ng  = (warp >> 1) & 1;
    const int kq1 = warp >> 2;
    const int n2 = (warp >> 2) * 32 + lane;
    const int hp = warp & 3;
    const int h0 = blk * 8 + hp * 2;
    const int mh3 = warp & 3;
    const int kq3 = warp >> 2;
    const int nr = tid >> 2, pr = tid & 3;
    const int pg = blk * 4 + pr;

    const int a_r  = lane & 15;
    const int a_kb = (lane & 16) ? 16 : 0;
    const int b_r  = (lane & 7) + ((lane & 16) ? 8 : 0);
    const int b_kb = (lane & 8) ? 16 : 0;

    const float wci0 = WC[h0],             wci1 = WC[h0 + 1];
    const float wcf0 = WC[H_DIM + h0],     wcf1 = WC[H_DIM + h0 + 1];
    const float wco0 = WC[2 * H_DIM + h0], wco1 = WC[2 * H_DIM + h0 + 1];

    long long first = *(const long long*)Lraw;
    long long len_r;
    if (first >= 1 && first <= (long long)T_STEPS)
        len_r = ((const long long*)Lraw)[nr];
    else
        len_r = (long long)((const int*)Lraw)[nr];

    float c0 = 0.0f, c1 = 0.0f;
    unsigned sense = 0;

    if (tid == 0) g_flags[blk * 64] = 0u;
    grid_barrier(sense);     // all flag resets visible before any waits

#pragma unroll 1
    for (int t = 0; t < T_STEPS; t++) {
        const unsigned tgt_r = (unsigned)(2 * t);        // r(t-1) published
        const unsigned tgt_h = (unsigned)(2 * t + 1);    // h(t)  published

        // ---- stage r(t-1): 4 k-chunks with per-group waits (rotated start) ----
        if (t > 0) {
            const char* rsrc = (const char*)g_rb[(t - 1) & 1];
#pragma unroll 1
            for (int qi = 0; qi < 4; qi++) {
                const int q = (qi + grot) & 3;
                waitg(q, tgt_r);
                for (int g = tid; g < 2048; g += NTHR) {
                    int row = g >> 5, gi = g & 31;
                    if (gi < 16)
                        cpa16s(sb + R_REG + row * 2064 + q * 256 + gi * 16,
                               rsrc + row * 2048 + q * 256 + gi * 16);
                    else
                        cpa16s(sb + R_REG + row * 2064 + 1024 + q * 256 + (gi - 16) * 16,
                               rsrc + row * 2048 + 1024 + q * 256 + (gi - 16) * 16);
                }
                CP_COMMIT();
            }
        }

        // ---- pre[t] loads (overlap with staging in flight) ----
        float pv[8];
        if (warp < 8) {
            const int m = t * N_BATCH + n2;
#pragma unroll
            for (int g = 0; g < 4; g++)
#pragma unroll
                for (int j = 0; j < 2; j++)
                    pv[g * 2 + j] =
                        __ldg(g_pre + (size_t)(g * H_DIM + h0 + j) * M_TOTAL + m);
        }

        // ---- phase 1: partial[n][gcol] = r . wr  (bf16-split HMMA) ----
        if (t > 0) {
            CP_WAIT0();
            __syncthreads();

            float acc[2][2][4];
#pragma unroll
            for (int a = 0; a < 2; a++)
#pragma unroll
                for (int b = 0; b < 2; b++)
#pragma unroll
                    for (int c = 0; c < 4; c++) acc[a][b][c] = 0.0f;

#pragma unroll 2
            for (int j = 0; j < 8; j++) {
                const int kb = (kq1 * 128 + j * 16) * 2;
                uint32_t bh[4], bl[4];
                const uint32_t brow = (uint32_t)(ng * 16 + b_r);
                ldm_x4(bh[0], bh[1], bh[2], bh[3],
                       sb + R_W1HI + brow * 1040 + kb + b_kb);
                ldm_x4(bl[0], bl[1], bl[2], bl[3],
                       sb + R_W1LO + brow * 1040 + kb + b_kb);
#pragma unroll
                for (int mi = 0; mi < 2; mi++) {
                    const uint32_t arow = (uint32_t)(mh * 32 + mi * 16 + a_r);
                    uint32_t ah[4], al[4];
                    ldm_x4(ah[0], ah[1], ah[2], ah[3],
                           sb + R_REG + arow * 2064 + kb + a_kb);
                    ldm_x4(al[0], al[1], al[2], al[3],
                           sb + R_REG + arow * 2064 + 1024 + kb + a_kb);
#pragma unroll
                    for (int nj = 0; nj < 2; nj++) {
                        mma_bf16(acc[mi][nj], ah, &bh[nj * 2]);
                        mma_bf16(acc[mi][nj], al, &bh[nj * 2]);
                        mma_bf16(acc[mi][nj], ah, &bl[nj * 2]);
                    }
                }
            }
            __syncthreads();

#pragma unroll
            for (int mi = 0; mi < 2; mi++)
#pragma unroll
                for (int nj = 0; nj < 2; nj++) {
                    const int n  = mh * 32 + mi * 16 + (lane >> 2);
                    const int gc = ng * 16 + nj * 8 + (lane & 3) * 2;
                    float2 v0 = { acc[mi][nj][0], acc[mi][nj][1] };
                    float2 v1 = { acc[mi][nj][2], acc[mi][nj][3] };
                    *(float2*)&part[(kq1 * 64 + n) * 38 + gc] = v0;
                    *(float2*)&part[(kq1 * 64 + n + 8) * 38 + gc] = v1;
                }
            __syncthreads();
        }

        // ---- phase 2: gates; h -> g_hb[t&1] ----
        if (warp < 8) {
            float gv[8];
#pragma unroll
            for (int q = 0; q < 8; q++) gv[q] = pv[q];
            if (t > 0) {
#pragma unroll
                for (int gate = 0; gate < 4; gate++) {
                    const int gc = gate * 8 + hp * 2;
#pragma unroll
                    for (int kq = 0; kq < 4; kq++) {
                        float2 v = *(const float2*)&part[(kq * 64 + n2) * 38 + gc];
                        gv[gate * 2]     += v.x;
                        gv[gate * 2 + 1] += v.y;
                    }
                }
            }
            float in0 = sigmoidf_(gv[0] + wci0 * c0);
            float fg0 = sigmoidf_(gv[2] + wcf0 * c0);
            float cc0 = fg0 * c0 + in0 * tanhf_(gv[6]);
            float og0 = sigmoidf_(gv[4] + wco0 * cc0);
            float hv0 = og0 * tanhf_(cc0);
            c0 = cc0;
            float in1 = sigmoidf_(gv[1] + wci1 * c1);
            float fg1 = sigmoidf_(gv[3] + wcf1 * c1);
            float cc1 = fg1 * c1 + in1 * tanhf_(gv[7]);
            float og1 = sigmoidf_(gv[5] + wco1 * cc1);
            float hv1 = og1 * tanhf_(cc1);
            c1 = cc1;

            __nv_bfloat16 h0b = __float2bfloat16(hv0);
            __nv_bfloat16 h1b = __float2bfloat16(hv1);
            __nv_bfloat16 l0b = __float2bfloat16(hv0 - __bfloat162float(h0b));
            __nv_bfloat16 l1b = __float2bfloat16(hv1 - __bfloat162float(h1b));
            uint32_t hi2 = (uint32_t)bf_bits(h0b) | ((uint32_t)bf_bits(h1b) << 16);
            uint32_t lo2 = (uint32_t)bf_bits(l0b) | ((uint32_t)bf_bits(l1b) << 16);
            stcg_u32(g_hb[t & 1] + n2 * 2048 + h0, hi2);
            stcg_u32(g_hb[t & 1] + n2 * 2048 + 1024 + h0, lo2);
        }
        __syncthreads();
        if (tid == 0) setflag(tgt_h);    // publish h(t)

        // ---- phase 3: r_new = h . wo, chunk pipeline with per-group waits -------------
        const char* hsrc = (const char*)g_hb[t & 1];
        // stage first two (rotated) chunks
#pragma unroll
        for (int ci = 0; ci < 2; ci++) {
            const int cc = (ci + grot) & 3;
            waitg(cc, tgt_h);
            const uint32_t hb = sb + R_REG + ci * HBUF1;
            for (int g = tid; g < 4096; g += NTHR) {
                int row = g >> 6, gi = g & 63;
                if (gi < 32)
                    cpa16s(hb + row * 1040 + gi * 16,
                           hsrc + row * 4096 + cc * 512 + gi * 16);
                else
                    cpa16s(hb + row * 1040 + 512 + (gi - 32) * 16,
                           hsrc + row * 4096 + 2048 + cc * 512 + (gi - 32) * 16);
            }
            CP_COMMIT();
        }

        float acc3[4] = {0.0f, 0.0f, 0.0f, 0.0f};
#pragma unroll 1
        for (int ci = 0; ci < 4; ci++) {
            const int cc = (ci + grot) & 3;
            if (ci < 3) CP_WAIT1(); else CP_WAIT0();
            __syncthreads();
            const uint32_t hb = sb + R_REG + (ci & 1) * HBUF1;
#pragma unroll
            for (int j = 0; j < 4; j++) {
                const int jj = kq3 * 4 + j;
                const int kb = jj * 32;
                uint32_t ah[4], al[4], bh[2], bl[2];
                const uint32_t arow = (uint32_t)(mh3 * 16 + a_r);
                ldm_x4(ah[0], ah[1], ah[2], ah[3], hb + arow * 1040 + kb + a_kb);
                ldm_x4(al[0], al[1], al[2], al[3], hb + arow * 1040 + 512 + kb + a_kb);
                const int kob = (cc * 256 + jj * 16) * 2;
                const uint32_t brow = (uint32_t)(lane & 3);
                ldm_x2(bh[0], bh[1], sb + R_WOHI + brow * 2064 + kob + b_kb);
                ldm_x2(bl[0], bl[1], sb + R_WOLO + brow * 2064 + kob + b_kb);
                mma_bf16(acc3, ah, bh);
                mma_bf16(acc3, al, bh);
                mma_bf16(acc3, ah, bl);
            }
            __syncthreads();
            if (ci < 2) {   // stage chunk ci+2 into freed buffer
                const int c2 = (ci + 2 + grot) & 3;
                waitg(c2, tgt_h);
                const uint32_t db = sb + R_REG + (ci & 1) * HBUF1;
                for (int g = tid; g < 4096; g += NTHR) {
                    int row = g >> 6, gi = g & 63;
                    if (gi < 32)
                        cpa16s(db + row * 1040 + gi * 16,
                               hsrc + row * 4096 + c2 * 512 + gi * 16);
                    else
                        cpa16s(db + row * 1040 + 512 + (gi - 32) * 16,
                               hsrc + row * 4096 + 2048 + c2 * 512 + (gi - 32) * 16);
                }
                CP_COMMIT();
            }
        }
        __syncthreads();

        if ((lane & 3) < 2) {
            const int n = mh3 * 16 + (lane >> 2);
            const int pc = (lane & 3) * 2;
            float2 v0 = { acc3[0], acc3[1] };
            float2 v1 = { acc3[2], acc3[3] };
            *(float2*)&part3[(kq3 * 64 + n) * 6 + pc] = v0;
            *(float2*)&part3[(kq3 * 64 + n + 8) * 6 + pc] = v1;
        }
        __syncthreads();

        if (tid < 256) {
            float v = 0.0f;
#pragma unroll
            for (int kq = 0; kq < 4; kq++) v += part3[(kq * 64 + nr) * 6 + pr];
            out[(size_t)(t * N_BATCH + nr) * P_DIM + pg] = (t < len_r) ? v : 0.0f;
            __nv_bfloat16 hb16 = __float2bfloat16(v);
            __nv_bfloat16 lb16 = __float2bfloat16(v - __bfloat162float(hb16));
            stcg_u16(g_rb[t & 1] + nr * 1024 + pg, bf_bits(hb16));
            stcg_u16(g_rb[t & 1] + nr * 1024 + 512 + pg, bf_bits(lb16));
        }
        __syncthreads();
        if (tid == 0) setflag(tgt_h + 1);   // publish r(t) = 2t+2
    }

    grid_barrier(sense);   // g_sense returns to launch-entry value (replay-safe)
}

// ---------------- launch ----------------------------------------------------------------
extern "C" void kernel_launch(void* const* d_in, const int* in_sizes, int n_in,
                              void* d_out, int out_size) {
    const float* x = nullptr;
    const void*  lengths = nullptr;
    const float* wx_w = nullptr;
    const float* wx_b = nullptr;
    const float* wr_w = nullptr;
    const float* wo_w = nullptr;
    const float* wc = nullptr;

    for (int i = 0; i < n_in; i++) {
        int s = in_sizes[i];
        if      (s == T_STEPS * N_BATCH * C_IN) x = (const float*)d_in[i];
        else if (s == N_BATCH)                  lengths = d_in[i];
        else if (s == 4 * H_DIM * C_IN) {
            if (!wx_w) wx_w = (const float*)d_in[i];
            else       wr_w = (const float*)d_in[i];
        }
        else if (s == 4 * H_DIM)                wx_b = (const float*)d_in[i];
        else if (s == P_DIM * H_DIM)            wo_w = (const float*)d_in[i];
        else if (s == 3 * H_DIM)                wc = (const float*)d_in[i];
    }

    __nv_bfloat16 *xs, *ws;
    cudaGetSymbolAddress((void**)&xs, g_xs);
    cudaGetSymbolAddress((void**)&ws, g_ws);

    split3<<<4096, 256>>>(x,    xs, M_TOTAL * C_IN, 0);
    split3<<<1024, 256>>>(wx_w, ws, G4H * C_IN, 1);

    cudaFuncSetAttribute(hmma_pre, cudaFuncAttributeMaxDynamicSharedMemorySize, PRE_SMEM);
    dim3 gridp(G4H / PBM, M_TOTAL / PBN);
    hmma_pre<<<gridp, PTHR, PRE_SMEM>>>(wx_b);

    cudaFuncSetAttribute(lstm_rec, cudaFuncAttributeMaxDynamicSharedMemorySize, REC_SMEM);
    lstm_rec<<<NBLK, NTHR, REC_SMEM>>>(wr_w, wo_w, wc, lengths, (float*)d_out);
}

// round 10
// speedup vs baseline: 1.1646x; 1.1646x over previous
#include <cuda_runtime.h>
#include <cuda_bf16.h>
#include <cstdint>

#define T_STEPS 512
#define N_BATCH 64
#define C_IN    512
#define H_DIM   1024
#define P_DIM   512
#define G4H     4096
#define M_TOTAL (T_STEPS * N_BATCH)   /* 32768 */
#define NBLK    128
#define NTHR    512
#define KSPLIT  1536                  /* pre-GEMM bf16-split K */

typedef unsigned long long u64t;

// ---------------- scratch (device globals: no runtime allocation allowed) -------------
__device__ float g_pre[(size_t)G4H * M_TOTAL];        // pre^T [g][m], 512 MB
__device__ __nv_bfloat16 g_rb[N_BATCH * 1024];        // r state: [n][hi 512 | lo 512]
__device__ __nv_bfloat16 g_hb[N_BATCH * 2048];        // h state: [n][hi 1024 | lo 1024]
__device__ unsigned g_count;                          // legacy barrier counter
__device__ unsigned g_sense;                          // legacy barrier sense
__device__ unsigned g_flags[NBLK * 64];               // flag barrier: 1 flag / 256B line
__device__ __nv_bfloat16 g_xs[(size_t)M_TOTAL * KSPLIT];  // x split  [m][1536]
__device__ __nv_bfloat16 g_ws[(size_t)G4H * KSPLIT];      // wx split [g][1536]

// ---------------- small helpers --------------------------------------------------------
__device__ __forceinline__ void cpa16s(uint32_t smem_dst, const void* gsrc) {
    asm volatile("cp.async.cg.shared.global [%0], [%1], 16;" :: "r"(smem_dst), "l"(gsrc));
}
#define CP_COMMIT() asm volatile("cp.async.commit_group;" ::: "memory")
#define CP_WAIT0()  asm volatile("cp.async.wait_group 0;" ::: "memory")
#define CP_WAIT1()  asm volatile("cp.async.wait_group 1;" ::: "memory")

__device__ __forceinline__ float sigmoidf_(float x) {
    return 1.0f / (1.0f + __expf(-x));
}
__device__ __forceinline__ float tanhf_(float x) {
    float e = __expf(-2.0f * fabsf(x));
    float t = (1.0f - e) / (1.0f + e);
    return copysignf(t, x);
}
__device__ __forceinline__ uint32_t smem_u32(const void* p) {
    return (uint32_t)__cvta_generic_to_shared(p);
}
__device__ __forceinline__ void stcg_u32(void* p, uint32_t v) {
    asm volatile("st.global.cg.u32 [%0], %1;" :: "l"(p), "r"(v) : "memory");
}
__device__ __forceinline__ void stcg_u16(void* p, unsigned short v) {
    asm volatile("st.global.cg.u16 [%0], %1;" :: "l"(p), "h"(v) : "memory");
}
__device__ __forceinline__ unsigned short bf_bits(__nv_bfloat16 h) {
    unsigned short u; __builtin_memcpy(&u, &h, 2); return u;
}

// ---------------- HMMA helpers (sm_80+ baseline PTX: valid at compute_103) ------------
__device__ __forceinline__ void ldm_x4(uint32_t &r0, uint32_t &r1, uint32_t &r2,
                                       uint32_t &r3, uint32_t a) {
    asm volatile("ldmatrix.sync.aligned.m8n8.x4.shared.b16 {%0,%1,%2,%3}, [%4];"
                 : "=r"(r0), "=r"(r1), "=r"(r2), "=r"(r3) : "r"(a));
}
__device__ __forceinline__ void ldm_x2(uint32_t &r0, uint32_t &r1, uint32_t a) {
    asm volatile("ldmatrix.sync.aligned.m8n8.x2.shared.b16 {%0,%1}, [%2];"
                 : "=r"(r0), "=r"(r1) : "r"(a));
}
__device__ __forceinline__ void mma_bf16(float* d, const uint32_t* a, const uint32_t* b) {
    asm volatile("mma.sync.aligned.m16n8k16.row.col.f32.bf16.bf16.f32 "
                 "{%0,%1,%2,%3}, {%4,%5,%6,%7}, {%8,%9}, {%0,%1,%2,%3};"
                 : "+f"(d[0]), "+f"(d[1]), "+f"(d[2]), "+f"(d[3])
                 : "r"(a[0]), "r"(a[1]), "r"(a[2]), "r"(a[3]),
                   "r"(b[0]), "r"(b[1]));
}

// ---------------- legacy atomic grid barrier (2x per lstm_rec launch) -----------------
__device__ __forceinline__ void grid_barrier(unsigned &sense_local) {
    __syncthreads();
    if (threadIdx.x == 0) {
        unsigned s = sense_local ^ 1u;
        unsigned prev;
        asm volatile("atom.acq_rel.gpu.global.add.u32 %0, [%1], %2;"
                     : "=r"(prev) : "l"(&g_count), "r"(1u) : "memory");
        if (prev == gridDim.x - 1) {
            g_count = 0;
            asm volatile("st.release.gpu.global.u32 [%0], %1;"
                         :: "l"(&g_sense), "r"(s) : "memory");
        } else {
            unsigned v;
            do {
                asm volatile("ld.acquire.gpu.global.u32 %0, [%1];"
                             : "=r"(v) : "l"(&g_sense) : "memory");
            } while (v != s);
        }
    }
    __syncthreads();
    sense_local ^= 1u;
}

// ---------------- flag-array grid barrier (known good) --------------------------------
__device__ __forceinline__ void flag_barrier(unsigned s) {
    __syncthreads();
    if (threadIdx.x == 0)
        asm volatile("st.release.gpu.global.u32 [%0], %1;"
                     :: "l"(&g_flags[blockIdx.x * 64]), "r"(s) : "memory");
    if (threadIdx.x < NBLK) {
        const unsigned* p = &g_flags[threadIdx.x * 64];
        unsigned v;
        do {
            asm volatile("ld.acquire.gpu.global.u32 %0, [%1];"
                         : "=r"(v) : "l"(p) : "memory");
        } while ((int)(v - s) < 0);
    }
    __syncthreads();
}

// ---------------- Kernel 0: fp32 -> bf16 split, K-concatenated (pre-GEMM operands) ----
__global__ void split3(const float* __restrict__ src, __nv_bfloat16* __restrict__ dst,
                       int total, int mode) {
    for (int i = blockIdx.x * blockDim.x + threadIdx.x; i < total;
         i += gridDim.x * blockDim.x) {
        int row = i >> 9, k = i & 511;
        float v = src[i];
        __nv_bfloat16 h = __float2bfloat16(v);
        __nv_bfloat16 l = __float2bfloat16(v - __bfloat162float(h));
        __nv_bfloat16* d = dst + (size_t)row * KSPLIT + k;
        d[0] = h;
        d[512]  = mode ? h : l;
        d[1024] = mode ? l : h;
    }
}

// ---------------- Kernel 1: HMMA bf16-split pre-GEMM (unchanged, passing) -------------
#define PBM 256
#define PBN 128
#define PTHR 512
#define A_STG 20480
#define B_STG 10240
#define STG   (A_STG + B_STG)
#define PRE_SMEM (2 * STG)

__global__ __launch_bounds__(PTHR, 1)
void hmma_pre(const float* __restrict__ Bb) {
    extern __shared__ char smc[];
    const uint32_t sb = smem_u32(smc);
    const int tid = threadIdx.x, lane = tid & 31, warp = tid >> 5;
    const int wg = warp >> 2;
    const int wm = warp & 3;
    const int g0 = blockIdx.x * PBM;
    const int m0 = blockIdx.y * PBN;

    float acc[4][4][4];
#pragma unroll
    for (int a = 0; a < 4; a++)
#pragma unroll
        for (int b = 0; b < 4; b++)
#pragma unroll
            for (int c = 0; c < 4; c++) acc[a][b][c] = 0.0f;

    const int a_r = lane & 15;
    const int a_k = (lane & 16) ? 8 : 0;
    const int b_r = (lane & 7) + ((lane & 16) ? 8 : 0);
    const int b_k = (lane & 8) ? 8 : 0;

#pragma unroll 1
    for (int c = 0; c < KSPLIT / 32 + 1; c++) {
        if (c < KSPLIT / 32) {
            const int k0 = c * 32;
            const uint32_t ba = sb + (c & 1) * STG;
#pragma unroll
            for (int s = 0; s < 3; s++) {
                int f = tid + s * PTHR;
                if (f < 1024) {
                    int row = f >> 2, seg = f & 3;
                    cpa16s(ba + row * 80 + seg * 16,
                           g_ws + (size_t)(g0 + row) * KSPLIT + k0 + seg * 8);
                } else {
                    int f2 = f - 1024;
                    int row = f2 >> 2, seg = f2 & 3;
                    cpa16s(ba + A_STG + row * 80 + seg * 16,
                           g_xs + (size_t)(m0 + row) * KSPLIT + k0 + seg * 8);
                }
            }
            CP_COMMIT();
        }
        if (c == 0) continue;
        const int cc = c - 1;
        if (c < KSPLIT / 32) CP_WAIT1(); else CP_WAIT0();
        __syncthreads();

        const uint32_t abase = sb + (cc & 1) * STG + (wg * 64 + a_r) * 80 + a_k * 2;
        const uint32_t bbase = sb + (cc & 1) * STG + A_STG + (wm * 32 + b_r) * 80 + b_k * 2;
#pragma unroll
        for (int kh = 0; kh < 2; kh++) {
            uint32_t af[4][4], bf[2][4];
#pragma unroll
            for (int gi = 0; gi < 4; gi++)
                ldm_x4(af[gi][0], af[gi][1], af[gi][2], af[gi][3],
                       abase + gi * 16 * 80 + kh * 32);
#pragma unroll
            for (int bj = 0; bj < 2; bj++)
                ldm_x4(bf[bj][0], bf[bj][1], bf[bj][2], bf[bj][3],
                       bbase + bj * 16 * 80 + kh * 32);
#pragma unroll
            for (int gi = 0; gi < 4; gi++)
#pragma unroll
                for (int mj = 0; mj < 4; mj++)
                    mma_bf16(acc[gi][mj], af[gi], &bf[mj >> 1][(mj & 1) * 2]);
        }
        __syncthreads();
    }

#pragma unroll
    for (int gi = 0; gi < 4; gi++) {
        const int gr = g0 + wg * 64 + gi * 16 + (lane >> 2);
        const float blo = __ldg(Bb + gr);
        const float bhi = __ldg(Bb + gr + 8);
#pragma unroll
        for (int mj = 0; mj < 4; mj++) {
            const int mc = m0 + wm * 32 + mj * 8 + (lane & 3) * 2;
            float2 v0 = { acc[gi][mj][0] + blo, acc[gi][mj][1] + blo };
            float2 v1 = { acc[gi][mj][2] + bhi, acc[gi][mj][3] + bhi };
            *(float2*)(g_pre + (size_t)gr * M_TOTAL + mc) = v0;
            *(float2*)(g_pre + (size_t)(gr + 8) * M_TOTAL + mc) = v1;
        }
    }
}

// ---------------- Kernel 2: persistent LSTM recurrence (R6 + pipelined r staging) -----
// smem layout (bytes):
//   REG   @ 0       size 133120 : time-multiplexed
//            t>0: r staged [n(64)][hi 1024 | lo 1024 B] pitch 2064
//            then phase-1 partials: fp32 [kq(4)][n(64)][gcol pad 38]
//            then h chunks: 2 x ([n(64)][hi 512 | lo 512 B] pitch 1040 = 66560)
//            then phase-3 partials: fp32 [kq(4)][n(64)][p pad 6]
//   W1HI  @ 133120  size 33280 : [gcol(32)][512 bf16] pitch 1040
//   W1LO  @ 166400  size 33280
//   WOHI  @ 199680  size 8256  : [p(4)][1024 bf16] pitch 2064
//   WOLO  @ 207936  size 8256
#define R_REG   0
#define R_W1HI  133120
#define R_W1LO  166400
#define R_WOHI  199680
#define R_WOLO  207936
#define REC_SMEM 216192
#define HBUF1   66560

__global__ __launch_bounds__(NTHR, 1)
void lstm_rec(const float* __restrict__ WR, const float* __restrict__ WO,
              const float* __restrict__ WC, const void* __restrict__ Lraw,
              float* __restrict__ out) {
    extern __shared__ char sm[];
    const uint32_t sb = smem_u32(sm);
    float* part  = (float*)(sm + R_REG);
    float* part3 = (float*)(sm + R_REG);

    const int tid = threadIdx.x;
    const int blk = blockIdx.x;
    const int lane = tid & 31, warp = tid >> 5;

    // ---- build static weights in smem (bf16 hi/lo) ----
    {
        __nv_bfloat16* w1h = (__nv_bfloat16*)(sm + R_W1HI);
        __nv_bfloat16* w1l = (__nv_bfloat16*)(sm + R_W1LO);
        for (int idx = tid; idx < 32 * 512; idx += NTHR) {
            int gcol = idx >> 9, k = idx & 511;
            int gate = gcol >> 3, hl = gcol & 7;
            float v = WR[(size_t)(gate * H_DIM + blk * 8 + hl) * P_DIM + k];
            __nv_bfloat16 h = __float2bfloat16(v);
            w1h[gcol * 520 + k] = h;
            w1l[gcol * 520 + k] = __float2bfloat16(v - __bfloat162float(h));
        }
        __nv_bfloat16* woh = (__nv_bfloat16*)(sm + R_WOHI);
        __nv_bfloat16* wol = (__nv_bfloat16*)(sm + R_WOLO);
        for (int idx = tid; idx < 4 * 1024; idx += NTHR) {
            int p = idx >> 10, k = idx & 1023;
            float v = WO[(size_t)(blk * 4 + p) * H_DIM + k];
            __nv_bfloat16 h = __float2bfloat16(v);
            woh[p * 1032 + k] = h;
            wol[p * 1032 + k] = __float2bfloat16(v - __bfloat162float(h));
        }
    }

    // ---- roles (identical to R6) ----
    const int mh  = warp & 1;
    const int ng  = (warp >> 1) & 1;
    const int kq1 = warp >> 2;
    const int n2 = (warp >> 2) * 32 + lane;
    const int hp = warp & 3;
    const int h0 = blk * 8 + hp * 2;
    const int mh3 = warp & 3;
    const int kq3 = warp >> 2;
    const int nr = tid >> 2, pr = tid & 3;
    const int pg = blk * 4 + pr;

    const int a_r  = lane & 15;
    const int a_kb = (lane & 16) ? 16 : 0;
    const int b_r  = (lane & 7) + ((lane & 16) ? 8 : 0);
    const int b_kb = (lane & 8) ? 16 : 0;

    const float wci0 = WC[h0],             wci1 = WC[h0 + 1];
    const float wcf0 = WC[H_DIM + h0],     wcf1 = WC[H_DIM + h0 + 1];
    const float wco0 = WC[2 * H_DIM + h0], wco1 = WC[2 * H_DIM + h0 + 1];

    long long first = *(const long long*)Lraw;
    long long len_r;
    if (first >= 1 && first <= (long long)T_STEPS)
        len_r = ((const long long*)Lraw)[nr];
    else
        len_r = (long long)((const int*)Lraw)[nr];

    float c0 = 0.0f, c1 = 0.0f;
    unsigned sense = 0;

    if (tid == 0) g_flags[blk * 64] = 0u;
    grid_barrier(sense);

    unsigned barno = 0;

#pragma unroll 1
    for (int t = 0; t < T_STEPS; t++) {
        // ---- stage r: two pipelined K-halves (hi+lo of k cols hv*256..hv*256+255) ----
        if (t > 0) {
            const char* rsrc = (const char*)g_rb;
#pragma unroll
            for (int hv = 0; hv < 2; hv++) {
                for (int g = tid; g < 4096; g += NTHR) {
                    int row = g >> 6, gi = g & 63;
                    if (gi < 32)
                        cpa16s(sb + R_REG + row * 2064 + hv * 512 + gi * 16,
                               rsrc + row * 2048 + hv * 512 + gi * 16);
                    else
                        cpa16s(sb + R_REG + row * 2064 + 1024 + hv * 512 + (gi - 32) * 16,
                               rsrc + row * 2048 + 1024 + hv * 512 + (gi - 32) * 16);
                }
                CP_COMMIT();
            }
        }

        // ---- pre[t] loads (overlap with staging) ----
        float pv[8];
        if (warp < 8) {
            const int m = t * N_BATCH + n2;
#pragma unroll
            for (int g = 0; g < 4; g++)
#pragma unroll
                for (int j = 0; j < 2; j++)
                    pv[g * 2 + j] =
                        __ldg(g_pre + (size_t)(g * H_DIM + h0 + j) * M_TOTAL + m);
        }

        // ---- phase 1: partial[n][gcol] = r . wr  (3-term bf16-split HMMA) ----
        // interleaved k16 mapping: half A: k16 = kq1*4 + j; half B: k16 = 16 + kq1*4 + j
        if (t > 0) {
            float acc[2][2][4];
#pragma unroll
            for (int a = 0; a < 2; a++)
#pragma unroll
                for (int b = 0; b < 2; b++)
#pragma unroll
                    for (int c = 0; c < 4; c++) acc[a][b][c] = 0.0f;

#pragma unroll
            for (int half = 0; half < 2; half++) {
                if (half == 0) { CP_WAIT1(); } else { CP_WAIT0(); }
                __syncthreads();
#pragma unroll
                for (int j = 0; j < 4; j++) {
                    const int k16 = half * 16 + kq1 * 4 + j;
                    const int kb = k16 * 32;
                    uint32_t bh[4], bl[4];
                    const uint32_t brow = (uint32_t)(ng * 16 + b_r);
                    ldm_x4(bh[0], bh[1], bh[2], bh[3],
                           sb + R_W1HI + brow * 1040 + kb + b_kb);
                    ldm_x4(bl[0], bl[1], bl[2], bl[3],
                           sb + R_W1LO + brow * 1040 + kb + b_kb);
#pragma unroll
                    for (int mi = 0; mi < 2; mi++) {
                        const uint32_t arow = (uint32_t)(mh * 32 + mi * 16 + a_r);
                        uint32_t ah[4], al[4];
                        ldm_x4(ah[0], ah[1], ah[2], ah[3],
                               sb + R_REG + arow * 2064 + kb + a_kb);
                        ldm_x4(al[0], al[1], al[2], al[3],
                               sb + R_REG + arow * 2064 + 1024 + kb + a_kb);
#pragma unroll
                        for (int nj = 0; nj < 2; nj++) {
                            mma_bf16(acc[mi][nj], ah, &bh[nj * 2]);
                            mma_bf16(acc[mi][nj], al, &bh[nj * 2]);
                            mma_bf16(acc[mi][nj], ah, &bl[nj * 2]);
                        }
                    }
                }
            }
            __syncthreads();   // all r reads done before partials overwrite region

#pragma unroll
            for (int mi = 0; mi < 2; mi++)
#pragma unroll
                for (int nj = 0; nj < 2; nj++) {
                    const int n  = mh * 32 + mi * 16 + (lane >> 2);
                    const int gc = ng * 16 + nj * 8 + (lane & 3) * 2;
                    float2 v0 = { acc[mi][nj][0], acc[mi][nj][1] };
                    float2 v1 = { acc[mi][nj][2], acc[mi][nj][3] };
                    *(float2*)&part[(kq1 * 64 + n) * 38 + gc] = v0;
                    *(float2*)&part[(kq1 * 64 + n + 8) * 38 + gc] = v1;
                }
            __syncthreads();
        }

        // ---- phase 2: gates (warps 0-7); h (hi+lo) -> g_hb ----
        if (warp < 8) {
            float gv[8];
#pragma unroll
            for (int q = 0; q < 8; q++) gv[q] = pv[q];
            if (t > 0) {
#pragma unroll
                for (int gate = 0; gate < 4; gate++) {
                    const int gc = gate * 8 + hp * 2;
#pragma unroll
                    for (int kq = 0; kq < 4; kq++) {
                        float2 v = *(const float2*)&part[(kq * 64 + n2) * 38 + gc];
                        gv[gate * 2]     += v.x;
                        gv[gate * 2 + 1] += v.y;
                    }
                }
            }
            float in0 = sigmoidf_(gv[0] + wci0 * c0);
            float fg0 = sigmoidf_(gv[2] + wcf0 * c0);
            float cc0 = fg0 * c0 + in0 * tanhf_(gv[6]);
            float og0 = sigmoidf_(gv[4] + wco0 * cc0);
            float hv0 = og0 * tanhf_(cc0);
            c0 = cc0;
            float in1 = sigmoidf_(gv[1] + wci1 * c1);
            float fg1 = sigmoidf_(gv[3] + wcf1 * c1);
            float cc1 = fg1 * c1 + in1 * tanhf_(gv[7]);
            float og1 = sigmoidf_(gv[5] + wco1 * cc1);
            float hv1 = og1 * tanhf_(cc1);
            c1 = cc1;

            __nv_bfloat16 h0b = __float2bfloat16(hv0);
            __nv_bfloat16 h1b = __float2bfloat16(hv1);
            __nv_bfloat16 l0b = __float2bfloat16(hv0 - __bfloat162float(h0b));
            __nv_bfloat16 l1b = __float2bfloat16(hv1 - __bfloat162float(h1b));
            uint32_t hi2 = (uint32_t)bf_bits(h0b) | ((uint32_t)bf_bits(h1b) << 16);
            uint32_t lo2 = (uint32_t)bf_bits(l0b) | ((uint32_t)bf_bits(l1b) << 16);
            stcg_u32(g_hb + n2 * 2048 + h0, hi2);
            stcg_u32(g_hb + n2 * 2048 + 1024 + h0, lo2);
        }

        flag_barrier(++barno);   // h complete chip-wide

        // ---- phase 3: r_new = h . wo (3-term, 4 pipelined hi+lo chunks; = R6) --------
        const char* hsrc = (const char*)g_hb;
#pragma unroll
        for (int c0i = 0; c0i < 2; c0i++) {
            const uint32_t hb = sb + R_REG + c0i * HBUF1;
            for (int g = tid; g < 4096; g += NTHR) {
                int row = g >> 6, gi = g & 63;
                if (gi < 32)
                    cpa16s(hb + row * 1040 + gi * 16,
                           hsrc + row * 4096 + c0i * 512 + gi * 16);
                else
                    cpa16s(hb + row * 1040 + 512 + (gi - 32) * 16,
                           hsrc + row * 4096 + 2048 + c0i * 512 + (gi - 32) * 16);
            }
            CP_COMMIT();
        }

        float acc3[4] = {0.0f, 0.0f, 0.0f, 0.0f};
#pragma unroll 1
        for (int c = 0; c < 4; c++) {
            if (c < 3) CP_WAIT1(); else CP_WAIT0();
            __syncthreads();
            const uint32_t hb = sb + R_REG + (c & 1) * HBUF1;
#pragma unroll
            for (int j = 0; j < 4; j++) {
                const int jj = kq3 * 4 + j;
                const int kb = jj * 32;
                uint32_t ah[4], al[4], bh[2], bl[2];
                const uint32_t arow = (uint32_t)(mh3 * 16 + a_r);
                ldm_x4(ah[0], ah[1], ah[2], ah[3], hb + arow * 1040 + kb + a_kb);
                ldm_x4(al[0], al[1], al[2], al[3], hb + arow * 1040 + 512 + kb + a_kb);
                const int kob = (c * 256 + jj * 16) * 2;
                const uint32_t brow = (uint32_t)(lane & 3);
                ldm_x2(bh[0], bh[1], sb + R_WOHI + brow * 2064 + kob + b_kb);
                ldm_x2(bl[0], bl[1], sb + R_WOLO + brow * 2064 + kob + b_kb);
                mma_bf16(acc3, ah, bh);
                mma_bf16(acc3, al, bh);
                mma_bf16(acc3, ah, bl);
            }
            __syncthreads();
            if (c < 2) {   // stage chunk c+2 into the buffer just freed
                const uint32_t db = sb + R_REG + (c & 1) * HBUF1;
                const int cc = c + 2;
                for (int g = tid; g < 4096; g += NTHR) {
                    int row = g >> 6, gi = g & 63;
                    if (gi < 32)
                        cpa16s(db + row * 1040 + gi * 16,
                               hsrc + row * 4096 + cc * 512 + gi * 16);
                    else
                        cpa16s(db + row * 1040 + 512 + (gi - 32) * 16,
                               hsrc + row * 4096 + 2048 + cc * 512 + (gi - 32) * 16);
                }
                CP_COMMIT();
            }
        }
        __syncthreads();

        // phase-3 partials: [kq][n][6] fp32 (real p cols 0-3: lanes (lane&3)<2)
        if ((lane & 3) < 2) {
            const int n = mh3 * 16 + (lane >> 2);
            const int pc = (lane & 3) * 2;
            float2 v0 = { acc3[0], acc3[1] };
            float2 v1 = { acc3[2], acc3[3] };
            *(float2*)&part3[(kq3 * 64 + n) * 6 + pc] = v0;
            *(float2*)&part3[(kq3 * 64 + n + 8) * 6 + pc] = v1;
        }
        __syncthreads();

        if (tid < 256) {
            float v = 0.0f;
#pragma unroll
            for (int kq = 0; kq < 4; kq++) v += part3[(kq * 64 + nr) * 6 + pr];
            out[(size_t)(t * N_BATCH + nr) * P_DIM + pg] = (t < len_r) ? v : 0.0f;
            __nv_bfloat16 hb16 = __float2bfloat16(v);
            __nv_bfloat16 lb16 = __float2bfloat16(v - __bfloat162float(hb16));
            stcg_u16(g_rb + nr * 1024 + pg, bf_bits(hb16));
            stcg_u16(g_rb + nr * 1024 + 512 + pg, bf_bits(lb16));
        }

        flag_barrier(++barno);   // r complete chip-wide
    }

    grid_barrier(sense);   // g_sense returns to launch-entry value (replay-safe)
}

// ---------------- launch ----------------------------------------------------------------
extern "C" void kernel_launch(void* const* d_in, const int* in_sizes, int n_in,
                              void* d_out, int out_size) {
    const float* x = nullptr;
    const void*  lengths = nullptr;
    const float* wx_w = nullptr;
    const float* wx_b = nullptr;
    const float* wr_w = nullptr;
    const float* wo_w = nullptr;
    const float* wc = nullptr;

    for (int i = 0; i < n_in; i++) {
        int s = in_sizes[i];
        if      (s == T_STEPS * N_BATCH * C_IN) x = (const float*)d_in[i];
        else if (s == N_BATCH)                  lengths = d_in[i];
        else if (s == 4 * H_DIM * C_IN) {
            if (!wx_w) wx_w = (const float*)d_in[i];
            else       wr_w = (const float*)d_in[i];
        }
        else if (s == 4 * H_DIM)                wx_b = (const float*)d_in[i];
        else if (s == P_DIM * H_DIM)            wo_w = (const float*)d_in[i];
        else if (s == 3 * H_DIM)                wc = (const float*)d_in[i];
    }

    __nv_bfloat16 *xs, *ws;
    cudaGetSymbolAddress((void**)&xs, g_xs);
    cudaGetSymbolAddress((void**)&ws, g_ws);

    split3<<<4096, 256>>>(x,    xs, M_TOTAL * C_IN, 0);
    split3<<<1024, 256>>>(wx_w, ws, G4H * C_IN, 1);

    cudaFuncSetAttribute(hmma_pre, cudaFuncAttributeMaxDynamicSharedMemorySize, PRE_SMEM);
    dim3 gridp(G4H / PBM, M_TOTAL / PBN);
    hmma_pre<<<gridp, PTHR, PRE_SMEM>>>(wx_b);

    cudaFuncSetAttribute(lstm_rec, cudaFuncAttributeMaxDynamicSharedMemorySize, REC_SMEM);
    lstm_rec<<<NBLK, NTHR, REC_SMEM>>>(wr_w, wo_w, wc, lengths, (float*)d_out);
}

// round 12
// speedup vs baseline: 1.2751x; 1.0949x over previous
#include <cuda_runtime.h>
#include <cuda_bf16.h>
#include <cstdint>

#define T_STEPS 512
#define N_BATCH 64
#define C_IN    512
#define H_DIM   1024
#define P_DIM   512
#define G4H     4096
#define M_TOTAL (T_STEPS * N_BATCH)   /* 32768 */
#define NBLK    128
#define NTHR    512

// ---------------- scratch (device globals: no runtime allocation allowed) -------------
__device__ float g_pre[(size_t)G4H * M_TOTAL];            // pre^T [g][m], 512 MB
__device__ float g_wc[(size_t)G4H * H_DIM];               // Wcomb = Wr@Wo fp32, 16 MB
__device__ __nv_bfloat16 g_hall[(size_t)M_TOTAL * 2048];  // hvec archive [t*64+n][hi1024|lo1024]
__device__ unsigned g_count;                              // legacy barrier counter
__device__ unsigned g_sense;                              // legacy barrier sense
__device__ unsigned g_flags[NBLK * 64];                   // flag barrier: 1 flag / 256B line
__device__ __nv_bfloat16 g_xs[(size_t)M_TOTAL * 1536];    // x split   [m][hi|lo|hi]
__device__ __nv_bfloat16 g_ws[(size_t)G4H * 1536];        // wx split  [g][hi|hi|lo]
__device__ __nv_bfloat16 g_wrs[(size_t)G4H * 1536];       // wr split  [g][hi|hi|lo]
__device__ __nv_bfloat16 g_wts[(size_t)H_DIM * 1536];     // wo^T split[h][hi|lo|hi]
__device__ __nv_bfloat16 g_wos[(size_t)P_DIM * 3072];     // wo split  [p][hi|hi|lo] (K=1024)

// ---------------- small helpers --------------------------------------------------------
__device__ __forceinline__ void cpa16s(uint32_t smem_dst, const void* gsrc) {
    asm volatile("cp.async.cg.shared.global [%0], [%1], 16;" :: "r"(smem_dst), "l"(gsrc));
}
#define CP_COMMIT() asm volatile("cp.async.commit_group;" ::: "memory")
#define CP_WAIT0()  asm volatile("cp.async.wait_group 0;" ::: "memory")
#define CP_WAIT1()  asm volatile("cp.async.wait_group 1;" ::: "memory")

__device__ __forceinline__ float sigmoidf_(float x) {
    return 1.0f / (1.0f + __expf(-x));
}
__device__ __forceinline__ float tanhf_(float x) {
    float e = __expf(-2.0f * fabsf(x));
    float t = (1.0f - e) / (1.0f + e);
    return copysignf(t, x);
}
__device__ __forceinline__ uint32_t smem_u32(const void* p) {
    return (uint32_t)__cvta_generic_to_shared(p);
}
__device__ __forceinline__ void stcg_u32(void* p, uint32_t v) {
    asm volatile("st.global.cg.u32 [%0], %1;" :: "l"(p), "r"(v) : "memory");
}
__device__ __forceinline__ unsigned short bf_bits(__nv_bfloat16 h) {
    unsigned short u; __builtin_memcpy(&u, &h, 2); return u;
}

// ---------------- HMMA helpers (sm_80+ baseline PTX: valid at compute_103) ------------
__device__ __forceinline__ void ldm_x4(uint32_t &r0, uint32_t &r1, uint32_t &r2,
                                       uint32_t &r3, uint32_t a) {
    asm volatile("ldmatrix.sync.aligned.m8n8.x4.shared.b16 {%0,%1,%2,%3}, [%4];"
                 : "=r"(r0), "=r"(r1), "=r"(r2), "=r"(r3) : "r"(a));
}
__device__ __forceinline__ void mma_bf16(float* d, const uint32_t* a, const uint32_t* b) {
    asm volatile("mma.sync.aligned.m16n8k16.row.col.f32.bf16.bf16.f32 "
                 "{%0,%1,%2,%3}, {%4,%5,%6,%7}, {%8,%9}, {%0,%1,%2,%3};"
                 : "+f"(d[0]), "+f"(d[1]), "+f"(d[2]), "+f"(d[3])
                 : "r"(a[0]), "r"(a[1]), "r"(a[2]), "r"(a[3]),
                   "r"(b[0]), "r"(b[1]));
}

// ---------------- legacy atomic grid barrier (2x per lstm_rec launch) -----------------
__device__ __forceinline__ void grid_barrier(unsigned &sense_local) {
    __syncthreads();
    if (threadIdx.x == 0) {
        unsigned s = sense_local ^ 1u;
        unsigned prev;
        asm volatile("atom.acq_rel.gpu.global.add.u32 %0, [%1], %2;"
                     : "=r"(prev) : "l"(&g_count), "r"(1u) : "memory");
        if (prev == gridDim.x - 1) {
            g_count = 0;
            asm volatile("st.release.gpu.global.u32 [%0], %1;"
                         :: "l"(&g_sense), "r"(s) : "memory");
        } else {
            unsigned v;
            do {
                asm volatile("ld.acquire.gpu.global.u32 %0, [%1];"
                             : "=r"(v) : "l"(&g_sense) : "memory");
            } while (v != s);
        }
    }
    __syncthreads();
    sense_local ^= 1u;
}

// ---------------- flag-array grid barrier (known good) --------------------------------
__device__ __forceinline__ void flag_barrier(unsigned s) {
    __syncthreads();
    if (threadIdx.x == 0)
        asm volatile("st.release.gpu.global.u32 [%0], %1;"
                     :: "l"(&g_flags[blockIdx.x * 64]), "r"(s) : "memory");
    if (threadIdx.x < NBLK) {
        const unsigned* p = &g_flags[threadIdx.x * 64];
        unsigned v;
        do {
            asm volatile("ld.acquire.gpu.global.u32 %0, [%1];"
                         : "=r"(v) : "l"(p) : "memory");
        } while ((int)(v - s) < 0);
    }
    __syncthreads();
}

// ---------------- split kernels --------------------------------------------------------
// K-concatenated bf16 hi/lo split. mode 0: [hi|lo|hi]; mode 1: [hi|hi|lo].
__global__ void splitk(const float* __restrict__ src, __nv_bfloat16* __restrict__ dst,
                       int total, int rl2, int mode) {
    const int rowmask = (1 << rl2) - 1;
    const int rowlen = 1 << rl2;
    for (int i = blockIdx.x * blockDim.x + threadIdx.x; i < total;
         i += gridDim.x * blockDim.x) {
        int row = i >> rl2, k = i & rowmask;
        float v = src[i];
        __nv_bfloat16 h = __float2bfloat16(v);
        __nv_bfloat16 l = __float2bfloat16(v - __bfloat162float(h));
        __nv_bfloat16* d = dst + (size_t)row * 3 * rowlen + k;
        d[0] = h;
        d[rowlen]     = mode ? h : l;
        d[2 * rowlen] = mode ? l : h;
    }
}
// Transpose-split for Wo: wo[p][h] -> wts[h][hi(512)|lo(512)|hi(512)] over p.
__global__ void splitt(const float* __restrict__ wo, __nv_bfloat16* __restrict__ dst) {
    for (int i = blockIdx.x * blockDim.x + threadIdx.x; i < P_DIM * H_DIM;
         i += gridDim.x * blockDim.x) {
        int p = i >> 10, h = i & 1023;
        float v = wo[i];
        __nv_bfloat16 hi = __float2bfloat16(v);
        __nv_bfloat16 lo = __float2bfloat16(v - __bfloat162float(hi));
        __nv_bfloat16* d = dst + (size_t)h * 1536 + p;
        d[0] = hi; d[512] = lo; d[1024] = hi;
    }
}

// ---------------- generic HMMA GEMM (proven R5 mainloop) -------------------------------
// C[M(gr) x N(mc)] = A[gr][ktot] . B[mc][ktot].  CTA tile 256x128, 512 thr, BK=32.
// mode 0: C -> g_pre (bias add, [g][m] store)   [pre-GEMM]
// mode 1: C -> g_wc fp32 [g][h] row-major       [Wcomb]
// mode 2: C -> outp masked by lengths, [m][p]   [final output]
#define PTHR 512
#define A_STG 20480
#define B_STG 10240
#define STG   (A_STG + B_STG)
#define GEN_SMEM (2 * STG + 256)

__global__ __launch_bounds__(PTHR, 1)
void hmma_gemm(const __nv_bfloat16* __restrict__ A, const __nv_bfloat16* __restrict__ B,
               int apitch, int bpitch, int ktot, int bwrapk, int mode,
               const float* __restrict__ bias, float* __restrict__ outp,
               const void* __restrict__ Lraw) {
    extern __shared__ char smc[];
    const uint32_t sb = smem_u32(smc);
    int* s_len = (int*)(smc + 2 * STG);
    const int tid = threadIdx.x, lane = tid & 31, warp = tid >> 5;
    const int wg = warp >> 2;
    const int wm = warp & 3;
    const int g0 = blockIdx.x * 256;
    const int m0 = blockIdx.y * 128;

    if (mode == 2 && tid < 64) {
        long long first = *(const long long*)Lraw;
        bool i64 = (first >= 1 && first <= (long long)T_STEPS);
        long long L = i64 ? ((const long long*)Lraw)[tid]
                          : (long long)((const int*)Lraw)[tid];
        s_len[tid] = (int)L;
    }

    float acc[4][4][4];
#pragma unroll
    for (int a = 0; a < 4; a++)
#pragma unroll
        for (int b = 0; b < 4; b++)
#pragma unroll
            for (int c = 0; c < 4; c++) acc[a][b][c] = 0.0f;

    const int a_r = lane & 15;
    const int a_k = (lane & 16) ? 8 : 0;
    const int b_r = (lane & 7) + ((lane & 16) ? 8 : 0);
    const int b_k = (lane & 8) ? 8 : 0;
    const int nk = ktot / 32;

#pragma unroll 1
    for (int c = 0; c < nk + 1; c++) {
        if (c < nk) {
            const int k0 = c * 32;
            const uint32_t ba = sb + (c & 1) * STG;
            const int kkb = (k0 >= bwrapk) ? k0 - bwrapk : k0;
#pragma unroll
            for (int s = 0; s < 3; s++) {
                int f = tid + s * PTHR;
                if (f < 1024) {
                    int row = f >> 2, seg = f & 3;
                    cpa16s(ba + row * 80 + seg * 16,
                           (const char*)A + (size_t)(g0 + row) * apitch + (size_t)k0 * 2 + seg * 16);
                } else {
                    int f2 = f - 1024;
                    int row = f2 >> 2, seg = f2 & 3;
                    cpa16s(ba + A_STG + row * 80 + seg * 16,
                           (const char*)B + (size_t)(m0 + row) * bpitch + (size_t)kkb * 2 + seg * 16);
                }
            }
            CP_COMMIT();
        }
        if (c == 0) continue;
        const int cc = c - 1;
        if (c < nk) CP_WAIT1(); else CP_WAIT0();
        __syncthreads();

        const uint32_t abase = sb + (cc & 1) * STG + (wg * 64 + a_r) * 80 + a_k * 2;
        const uint32_t bbase = sb + (cc & 1) * STG + A_STG + (wm * 32 + b_r) * 80 + b_k * 2;
#pragma unroll
        for (int kh = 0; kh < 2; kh++) {
            uint32_t af[4][4], bf[2][4];
#pragma unroll
            for (int gi = 0; gi < 4; gi++)
                ldm_x4(af[gi][0], af[gi][1], af[gi][2], af[gi][3],
                       abase + gi * 16 * 80 + kh * 32);
#pragma unroll
            for (int bj = 0; bj < 2; bj++)
                ldm_x4(bf[bj][0], bf[bj][1], bf[bj][2], bf[bj][3],
                       bbase + bj * 16 * 80 + kh * 32);
#pragma unroll
            for (int gi = 0; gi < 4; gi++)
#pragma unroll
                for (int mj = 0; mj < 4; mj++)
                    mma_bf16(acc[gi][mj], af[gi], &bf[mj >> 1][(mj & 1) * 2]);
        }
        __syncthreads();
    }

    if (mode == 0) {
#pragma unroll
        for (int gi = 0; gi < 4; gi++) {
            const int gr = g0 + wg * 64 + gi * 16 + (lane >> 2);
            const float blo = __ldg(bias + gr);
            const float bhi = __ldg(bias + gr + 8);
#pragma unroll
            for (int mj = 0; mj < 4; mj++) {
                const int mc = m0 + wm * 32 + mj * 8 + (lane & 3) * 2;
                float2 v0 = { acc[gi][mj][0] + blo, acc[gi][mj][1] + blo };
                float2 v1 = { acc[gi][mj][2] + bhi, acc[gi][mj][3] + bhi };
                *(float2*)(g_pre + (size_t)gr * M_TOTAL + mc) = v0;
                *(float2*)(g_pre + (size_t)(gr + 8) * M_TOTAL + mc) = v1;
            }
        }
    } else if (mode == 1) {
#pragma unroll
        for (int gi = 0; gi < 4; gi++) {
            const int gr = g0 + wg * 64 + gi * 16 + (lane >> 2);
#pragma unroll
            for (int mj = 0; mj < 4; mj++) {
                const int mc = m0 + wm * 32 + mj * 8 + (lane & 3) * 2;
                float2 v0 = { acc[gi][mj][0], acc[gi][mj][1] };
                float2 v1 = { acc[gi][mj][2], acc[gi][mj][3] };
                *(float2*)(g_wc + (size_t)gr * H_DIM + mc) = v0;
                *(float2*)(g_wc + (size_t)(gr + 8) * H_DIM + mc) = v1;
            }
        }
    } else {
#pragma unroll
        for (int gi = 0; gi < 4; gi++) {
            const int gr = g0 + wg * 64 + gi * 16 + (lane >> 2);
#pragma unroll
            for (int mj = 0; mj < 4; mj++) {
                const int mc = m0 + wm * 32 + mj * 8 + (lane & 3) * 2;
                int t0 = mc >> 6, n0 = mc & 63;
                int t1 = (mc + 1) >> 6, n1 = (mc + 1) & 63;
                bool k0v = (t0 < s_len[n0]), k1v = (t1 < s_len[n1]);
                outp[(size_t)mc * P_DIM + gr]           = k0v ? acc[gi][mj][0] : 0.0f;
                outp[(size_t)(mc + 1) * P_DIM + gr]     = k1v ? acc[gi][mj][1] : 0.0f;
                outp[(size_t)mc * P_DIM + gr + 8]       = k0v ? acc[gi][mj][2] : 0.0f;
                outp[(size_t)(mc + 1) * P_DIM + gr + 8] = k1v ? acc[gi][mj][3] : 0.0f;
            }
        }
    }
}

// ---------------- Kernel: persistent LSTM recurrence (fused Wcomb, 1 barrier/step) ----
// g(t) = pre(t) + hvec(t-1) @ Wcomb^T ; gates; hvec(t) -> g_hall. No r on critical path.
// smem: CHUNKS @0: 2 x [64 n][hi 256B | lo 256B] pitch 528 = 2x33792 (partials overlay)
//       WCHI @67584 / WCLO @133632: [gcol 32][1024 bf16] pitch 2064 = 66048 each
#define RC_WCH 67584
#define RC_WCL 133632
#define RC_TOT 199680

__global__ __launch_bounds__(NTHR, 1)
void lstm_rec(const float* __restrict__ WCp) {
    extern __shared__ char sm[];
    const uint32_t sb = smem_u32(sm);
    float* part = (float*)sm;

    const int tid = threadIdx.x;
    const int blk = blockIdx.x;
    const int lane = tid & 31, warp = tid >> 5;

    // ---- split Wcomb rows into smem bf16 hi/lo ----
    // IDENTITY row layout: smem row gcol = gate*8 + hl (must match the partial-store
    // mma-N space and the gate-read gc = gate*8 + hp*2). R10's permuted `col` here
    // was the 11.6%-error bug.
    {
        __nv_bfloat16* wch = (__nv_bfloat16*)(sm + RC_WCH);
        __nv_bfloat16* wcl = (__nv_bfloat16*)(sm + RC_WCL);
        for (int idx = tid; idx < 32 * 1024; idx += NTHR) {
            int gcol = idx >> 10, k = idx & 1023;
            int gate = gcol >> 3, hl = gcol & 7;
            float v = g_wc[(size_t)(gate * H_DIM + blk * 8 + hl) * H_DIM + k];
            __nv_bfloat16 h = __float2bfloat16(v);
            wch[gcol * 1032 + k] = h;
            wcl[gcol * 1032 + k] = __float2bfloat16(v - __bfloat162float(h));
        }
    }

    // ---- roles (formulas preserved from R9) ----
    const int mh  = warp & 1;
    const int ng  = (warp >> 1) & 1;
    const int kq1 = warp >> 2;
    const int n2 = (warp >> 2) * 32 + lane;
    const int hp = warp & 3;
    const int h0 = blk * 8 + hp * 2;

    const int a_r  = lane & 15;
    const int a_kb = (lane & 16) ? 16 : 0;
    const int b_r  = (lane & 7) + ((lane & 16) ? 8 : 0);
    const int b_kb = (lane & 8) ? 16 : 0;

    const float wci0 = WCp[h0],             wci1 = WCp[h0 + 1];
    const float wcf0 = WCp[H_DIM + h0],     wcf1 = WCp[H_DIM + h0 + 1];
    const float wco0 = WCp[2 * H_DIM + h0], wco1 = WCp[2 * H_DIM + h0 + 1];

    float c0 = 0.0f, c1 = 0.0f;
    unsigned sense = 0;

    if (tid == 0) g_flags[blk * 64] = 0u;
    grid_barrier(sense);

#pragma unroll 1
    for (int t = 0; t < T_STEPS; t++) {
        const char* hsrc = (const char*)g_hall + (size_t)(t - 1) * 64 * 4096;

        // stage chunks 0,1 of hvec(t-1): chunk c = k cols [c*128,(c+1)*128), hi+lo
        if (t > 0) {
#pragma unroll
            for (int ci = 0; ci < 2; ci++) {
                const uint32_t db = sb + ci * 33792;
                for (int g = tid; g < 2048; g += NTHR) {
                    int row = g >> 5, gi = g & 31;
                    if (gi < 16)
                        cpa16s(db + row * 528 + gi * 16,
                               hsrc + (size_t)row * 4096 + ci * 256 + gi * 16);
                    else
                        cpa16s(db + row * 528 + 256 + (gi - 16) * 16,
                               hsrc + (size_t)row * 4096 + 2048 + ci * 256 + (gi - 16) * 16);
                }
                CP_COMMIT();
            }
        }

        // pre[t] loads (overlap with staging)
        float pv[8];
        if (warp < 8) {
            const int m = t * N_BATCH + n2;
#pragma unroll
            for (int g = 0; g < 4; g++)
#pragma unroll
                for (int j = 0; j < 2; j++)
                    pv[g * 2 + j] =
                        __ldg(g_pre + (size_t)(g * H_DIM + h0 + j) * M_TOTAL + m);
        }

        // fused GEMM: partial[n][gcol] = hvec(t-1) . Wcomb  (3-term, 8 chunks)
        if (t > 0) {
            float acc[2][2][4];
#pragma unroll
            for (int a = 0; a < 2; a++)
#pragma unroll
                for (int b = 0; b < 2; b++)
#pragma unroll
                    for (int c = 0; c < 4; c++) acc[a][b][c] = 0.0f;

#pragma unroll 1
            for (int c = 0; c < 8; c++) {
                if (c < 7) CP_WAIT1(); else CP_WAIT0();
                __syncthreads();
                const uint32_t hb = sb + (c & 1) * 33792;
#pragma unroll
                for (int j = 0; j < 2; j++) {
                    const int k16l = kq1 * 2 + j;
                    const int kb  = k16l * 32;
                    const int kbw = (c * 8 + k16l) * 32;
                    uint32_t bh[4], bl[4];
                    const uint32_t brow = (uint32_t)(ng * 16 + b_r);
                    ldm_x4(bh[0], bh[1], bh[2], bh[3],
                           sb + RC_WCH + brow * 2064 + kbw + b_kb);
                    ldm_x4(bl[0], bl[1], bl[2], bl[3],
                           sb + RC_WCL + brow * 2064 + kbw + b_kb);
#pragma unroll
                    for (int mi = 0; mi < 2; mi++) {
                        const uint32_t arow = (uint32_t)(mh * 32 + mi * 16 + a_r);
                        uint32_t ah[4], al[4];
                        ldm_x4(ah[0], ah[1], ah[2], ah[3],
                               hb + arow * 528 + kb + a_kb);
                        ldm_x4(al[0], al[1], al[2], al[3],
                               hb + arow * 528 + 256 + kb + a_kb);
#pragma unroll
                        for (int nj = 0; nj < 2; nj++) {
                            mma_bf16(acc[mi][nj], ah, &bh[nj * 2]);
                            mma_bf16(acc[mi][nj], al, &bh[nj * 2]);
                            mma_bf16(acc[mi][nj], ah, &bl[nj * 2]);
                        }
                    }
                }
                __syncthreads();
                if (c < 6) {   // stage chunk c+2 into buffer just consumed
                    const uint32_t db = sb + (c & 1) * 33792;
                    const int c2 = c + 2;
                    for (int g = tid; g < 2048; g += NTHR) {
                        int row = g >> 5, gi = g & 31;
                        if (gi < 16)
                            cpa16s(db + row * 528 + gi * 16,
                                   hsrc + (size_t)row * 4096 + c2 * 256 + gi * 16);
                        else
                            cpa16s(db + row * 528 + 256 + (gi - 16) * 16,
                                   hsrc + (size_t)row * 4096 + 2048 + c2 * 256 + (gi - 16) * 16);
                    }
                    CP_COMMIT();
                }
            }

            // partials: [kq][n][38] fp32 (overlay chunk buffers; reads all done)
#pragma unroll
            for (int mi = 0; mi < 2; mi++)
#pragma unroll
                for (int nj = 0; nj < 2; nj++) {
                    const int n  = mh * 32 + mi * 16 + (lane >> 2);
                    const int gc = ng * 16 + nj * 8 + (lane & 3) * 2;
                    float2 v0 = { acc[mi][nj][0], acc[mi][nj][1] };
                    float2 v1 = { acc[mi][nj][2], acc[mi][nj][3] };
                    *(float2*)&part[(kq1 * 64 + n) * 38 + gc] = v0;
                    *(float2*)&part[(kq1 * 64 + n + 8) * 38 + gc] = v1;
                }
            __syncthreads();
        }

        // gates (warps 0-7); hvec (hi+lo) -> g_hall[t]
        if (warp < 8) {
            float gv[8];
#pragma unroll
            for (int q = 0; q < 8; q++) gv[q] = pv[q];
            if (t > 0) {
#pragma unroll
                for (int gate = 0; gate < 4; gate++) {
                    const int gc = gate * 8 + hp * 2;
#pragma unroll
                    for (int kq = 0; kq < 4; kq++) {
                        float2 v = *(const float2*)&part[(kq * 64 + n2) * 38 + gc];
                        gv[gate * 2]     += v.x;
                        gv[gate * 2 + 1] += v.y;
                    }
                }
            }
            float in0 = sigmoidf_(gv[0] + wci0 * c0);
            float fg0 = sigmoidf_(gv[2] + wcf0 * c0);
            float cc0 = fg0 * c0 + in0 * tanhf_(gv[6]);
            float og0 = sigmoidf_(gv[4] + wco0 * cc0);
            float hv0 = og0 * tanhf_(cc0);
            c0 = cc0;
            float in1 = sigmoidf_(gv[1] + wci1 * c1);
            float fg1 = sigmoidf_(gv[3] + wcf1 * c1);
            float cc1 = fg1 * c1 + in1 * tanhf_(gv[7]);
            float og1 = sigmoidf_(gv[5] + wco1 * cc1);
            float hv1 = og1 * tanhf_(cc1);
            c1 = cc1;

            __nv_bfloat16 h0b = __float2bfloat16(hv0);
            __nv_bfloat16 h1b = __float2bfloat16(hv1);
            __nv_bfloat16 l0b = __float2bfloat16(hv0 - __bfloat162float(h0b));
            __nv_bfloat16 l1b = __float2bfloat16(hv1 - __bfloat162float(h1b));
            uint32_t hi2 = (uint32_t)bf_bits(h0b) | ((uint32_t)bf_bits(h1b) << 16);
            uint32_t lo2 = (uint32_t)bf_bits(l0b) | ((uint32_t)bf_bits(l1b) << 16);
            stcg_u32(g_hall + (size_t)(t * 64 + n2) * 2048 + h0, hi2);
            stcg_u32(g_hall + (size_t)(t * 64 + n2) * 2048 + 1024 + h0, lo2);
        }

        flag_barrier((unsigned)(t + 1));   // hvec(t) complete chip-wide
    }

    grid_barrier(sense);   // g_sense returns to launch-entry value (replay-safe)
}

// ---------------- launch ----------------------------------------------------------------
extern "C" void kernel_launch(void* const* d_in, const int* in_sizes, int n_in,
                              void* d_out, int out_size) {
    const float* x = nullptr;
    const void*  lengths = nullptr;
    const float* wx_w = nullptr;
    const float* wx_b = nullptr;
    const float* wr_w = nullptr;
    const float* wo_w = nullptr;
    const float* wc = nullptr;

    for (int i = 0; i < n_in; i++) {
        int s = in_sizes[i];
        if      (s == T_STEPS * N_BATCH * C_IN) x = (const float*)d_in[i];
        else if (s == N_BATCH)                  lengths = d_in[i];
        else if (s == 4 * H_DIM * C_IN) {
            if (!wx_w) wx_w = (const float*)d_in[i];
            else       wr_w = (const float*)d_in[i];
        }
        else if (s == 4 * H_DIM)                wx_b = (const float*)d_in[i];
        else if (s == P_DIM * H_DIM)            wo_w = (const float*)d_in[i];
        else if (s == 3 * H_DIM)                wc = (const float*)d_in[i];
    }

    __nv_bfloat16 *xs, *ws, *wrs, *wts, *wos, *hall;
    cudaGetSymbolAddress((void**)&xs,  g_xs);
    cudaGetSymbolAddress((void**)&ws,  g_ws);
    cudaGetSymbolAddress((void**)&wrs, g_wrs);
    cudaGetSymbolAddress((void**)&wts, g_wts);
    cudaGetSymbolAddress((void**)&wos, g_wos);
    cudaGetSymbolAddress((void**)&hall, g_hall);

    // splits
    splitk<<<4096, 256>>>(x,    xs,  M_TOTAL * C_IN, 9, 0);
    splitk<<<1024, 256>>>(wx_w, ws,  G4H * C_IN,     9, 1);
    splitk<<<512,  256>>>(wr_w, wrs, G4H * P_DIM,    9, 1);
    splitt<<<512,  256>>>(wo_w, wts);
    splitk<<<512,  256>>>(wo_w, wos, P_DIM * H_DIM, 10, 1);

    cudaFuncSetAttribute(hmma_gemm, cudaFuncAttributeMaxDynamicSharedMemorySize, GEN_SMEM);

    // pre-GEMM: pre^T[g][m]
    {
        dim3 g(G4H / 256, M_TOTAL / 128);
        hmma_gemm<<<g, PTHR, GEN_SMEM>>>(ws, xs, 3072, 3072, 1536, 1 << 30, 0,
                                         wx_b, nullptr, nullptr);
    }
    // Wcomb = Wr @ Wo  (fp32 out)
    {
        dim3 g(G4H / 256, H_DIM / 128);
        hmma_gemm<<<g, PTHR, GEN_SMEM>>>(wrs, wts, 3072, 3072, 1536, 1 << 30, 1,
                                         nullptr, nullptr, nullptr);
    }
    // recurrence
    cudaFuncSetAttribute(lstm_rec, cudaFuncAttributeMaxDynamicSharedMemorySize, RC_TOT);
    lstm_rec<<<NBLK, NTHR, RC_TOT>>>(wc);
    // final output: out[m][p] = Hall[m] . Wo[p], masked by lengths
    {
        dim3 g(P_DIM / 256, M_TOTAL / 128);
        hmma_gemm<<<g, PTHR, GEN_SMEM>>>(wos, hall, 6144, 4096, 3072, 2048, 2,
                                         nullptr, (float*)d_out, lengths);
    }
}